// round 14
// baseline (speedup 1.0000x reference)
#include <cuda_runtime.h>
#include <cuda_bf16.h>
#include <cuda_fp16.h>

#define NTOK 16384
#define INF  512
#define HID  256
#define OUTF 16
#define NSTEPS 16
#define SIGMA2F 0.1f
#define LSCALE 16384.0f                 // 2^14: lifts L into e4m3 range
#define FIN_SCALE (SIGMA2F / LSCALE)
#define KSPLITS 32
#define KSEG (NTOK / KSPLITS)          // 512
#define KB_TOTAL (NTOK / 32)           // 512 32-k blocks
#define RT_TOTAL (NTOK / 16)           // 1024 row-tiles
#define SLICES_PER_CTA (KSEG / 32)     // 16
#define RGROUPS 128                    // partial row-groups (8 row-tiles each)
#define FBLOCKS 128                    // finalize blocks (128 rows each)
#define INIT_CTAS (NTOK / 8)           // 2048
#define CONV_CTAS (RT_TOTAL * 64)      // 65536

// Scratch (device globals: sanctioned, no allocation)
__device__ __align__(16) uint4          g_L8[(size_t)RT_TOTAL * KB_TOTAL * 32];  // 256 MB
__device__ __align__(16) float          g_U[2][NTOK * OUTF];                     // u fp32 master (ping-pong)
__device__ __align__(16) unsigned char  g_B8[2][NTOK * OUTF];                    // u e4m3 B-frag-major
__device__ __align__(16) float          g_P[2][NTOK * OUTF];                     // partials, double buffered (zero steady)
__device__ unsigned                     g_finkg[32];                             // per-k-group finalize counters (zero steady)

// ---------------------------------------------------------------------------
__device__ __forceinline__ unsigned short e4m3x2_pack(float hi, float lo) {
    unsigned short r;
    asm("cvt.rn.satfinite.e4m3x2.f32 %0, %1, %2;" : "=h"(r) : "f"(hi), "f"(lo));
    return r;
}
__device__ __forceinline__ unsigned pack4_e4m3(float4 f, float s) {
    const unsigned lo = e4m3x2_pack(f.y * s, f.x * s);
    const unsigned hi = e4m3x2_pack(f.w * s, f.z * s);
    return lo | (hi << 16);
}

// write one fp32 value (row r = k index, col c) into e4m3 B-fragment layout
__device__ __forceinline__ void write_bfrag8(unsigned char* Bf, int r, int c, float v) {
    const int sl = r >> 5, p = r & 31;
    const int g = c & 7;
    const int ph = p & 15;
    const int lane = g * 4 + (ph >> 2);
    const int word = (p >> 4) + 2 * (c >> 3);
    const unsigned short q = e4m3x2_pack(0.0f, v);
    Bf[sl * 512 + lane * 16 + word * 4 + (ph & 3)] = (unsigned char)(q & 0xFF);
}

// shared finalize body: u_out = u_in - FIN_SCALE * P_in; zero P_in; emit B8/u_out
__device__ __forceinline__ void finalize_rows(int fb, int tid, int pin, int pout,
                                              float* __restrict__ dst_f32,
                                              bool write_state) {
    const int r = fb * 128 + (tid >> 1);
    const int c0 = (tid & 1) * 8;
    const float* __restrict__ Ui = g_U[pin] + r * OUTF + c0;
    float* __restrict__ P  = g_P[pin] + r * OUTF + c0;

    float v[8];
    #pragma unroll
    for (int i = 0; i < 2; i++) {
        float4 u4 = *(const float4*)(Ui + 4 * i);
        float4 p4 = *(const float4*)(P + 4 * i);
        v[4*i+0] = u4.x - FIN_SCALE * p4.x;
        v[4*i+1] = u4.y - FIN_SCALE * p4.y;
        v[4*i+2] = u4.z - FIN_SCALE * p4.z;
        v[4*i+3] = u4.w - FIN_SCALE * p4.w;
        *(float4*)(P + 4 * i) = make_float4(0.f, 0.f, 0.f, 0.f);
        if (write_state)
            *(float4*)(g_U[pout] + r * OUTF + c0 + 4 * i)
                = make_float4(v[4*i+0], v[4*i+1], v[4*i+2], v[4*i+3]);
        if (dst_f32)
            *(float4*)(dst_f32 + r * OUTF + c0 + 4 * i)
                = make_float4(v[4*i+0], v[4*i+1], v[4*i+2], v[4*i+3]);
    }
    if (write_state) {
        unsigned char* __restrict__ Bf = g_B8[pout];
        #pragma unroll
        for (int c = 0; c < 8; c++) write_bfrag8(Bf, r, c0 + c, v[c]);
    }
}

// ---------------------------------------------------------------------------
// Fused prologue: blocks [0, INIT_CTAS) = init_u0; rest = convert_L (overlap).
// ---------------------------------------------------------------------------
#define CV_PAD 264
struct ProSmem {
    union {
        struct { float fs[8][INF]; float hs[8][HID]; } init;   // 24 KB
        float cv[16][CV_PAD];                                  // ~16.9 KB
    };
};

__global__ void __launch_bounds__(256) prologue(
    const float* __restrict__ L,
    const float* __restrict__ F,  const float* __restrict__ W1, const float* __restrict__ b1,
    const float* __restrict__ W2, const float* __restrict__ b2,
    const float* __restrict__ Ws, const float* __restrict__ bs)
{
    __shared__ ProSmem sm;
    const int tid = threadIdx.x;

    if (blockIdx.x < INIT_CTAS) {
        // ================= init_u0 =================
        float (*fs)[INF] = sm.init.fs;
        float (*hs)[HID] = sm.init.hs;
        const int rbase = blockIdx.x * 8;

        {
            const float4* Fv = (const float4*)(F + (size_t)rbase * INF);
            float4* fsv = (float4*)&fs[0][0];
            #pragma unroll 4
            for (int i = tid; i < 8 * INF / 4; i += 256) fsv[i] = Fv[i];
        }
        __syncthreads();

        {
            const int j = tid;
            float acc[8];
            const float bb = b1[j];
            #pragma unroll
            for (int rr = 0; rr < 8; rr++) acc[rr] = bb;
            #pragma unroll 4
            for (int k = 0; k < INF; k++) {
                const float w = W1[k * HID + j];
                #pragma unroll
                for (int rr = 0; rr < 8; rr++) acc[rr] = fmaf(fs[rr][k], w, acc[rr]);
            }
            #pragma unroll
            for (int rr = 0; rr < 8; rr++) {
                const float x = acc[rr];
                hs[rr][j] = x > 0.0f ? x : expm1f(x);
            }
        }
        __syncthreads();

        if (tid < 8 * OUTF) {
            const int rr = tid >> 4, c = tid & 15;
            float s0 = bs[c] + b2[c], s1 = 0.f, s2 = 0.f, s3 = 0.f;
            #pragma unroll 4
            for (int k = 0; k < INF; k += 4) {
                s0 = fmaf(fs[rr][k + 0], Ws[(k + 0) * OUTF + c], s0);
                s1 = fmaf(fs[rr][k + 1], Ws[(k + 1) * OUTF + c], s1);
                s2 = fmaf(fs[rr][k + 2], Ws[(k + 2) * OUTF + c], s2);
                s3 = fmaf(fs[rr][k + 3], Ws[(k + 3) * OUTF + c], s3);
            }
            #pragma unroll 4
            for (int j = 0; j < HID; j += 4) {
                s0 = fmaf(hs[rr][j + 0], W2[(j + 0) * OUTF + c], s0);
                s1 = fmaf(hs[rr][j + 1], W2[(j + 1) * OUTF + c], s1);
                s2 = fmaf(hs[rr][j + 2], W2[(j + 2) * OUTF + c], s2);
                s3 = fmaf(hs[rr][j + 3], W2[(j + 3) * OUTF + c], s3);
            }
            const float s = (s0 + s1) + (s2 + s3);
            const int r = rbase + rr;
            g_U[0][r * OUTF + c] = s;
            write_bfrag8(g_B8[0], r, c, s);
        }
    } else {
        // ================= convert_L (k32 fragment layout) =================
        float (*s)[CV_PAD] = sm.cv;
        const int blk = blockIdx.x - INIT_CTAS;   // 0..65535
        const int rt = blk >> 6;
        const int kg = blk & 63;

        const float* __restrict__ src = L + (size_t)rt * 16 * NTOK + kg * 256;
        #pragma unroll 4
        for (int j = tid; j < 16 * 64; j += 256) {
            const int row = j >> 6, c4 = j & 63;
            const float4 v = __ldcs((const float4*)(src + (size_t)row * NTOK + c4 * 4));
            *(float4*)&s[row][c4 * 4] = v;
        }
        __syncthreads();

        const int warp = tid >> 5, lane = tid & 31;
        const int g = lane >> 2, t = lane & 3;
        const int kb = kg * 8 + warp;            // global 32-k block
        const int c = warp * 32 + 4 * t;         // local col base

        const float4 f0 = *(const float4*)&s[g][c];
        const float4 f1 = *(const float4*)&s[g + 8][c];
        const float4 f2 = *(const float4*)&s[g][c + 16];
        const float4 f3 = *(const float4*)&s[g + 8][c + 16];
        uint4 o;
        o.x = pack4_e4m3(f0, LSCALE);
        o.y = pack4_e4m3(f1, LSCALE);
        o.z = pack4_e4m3(f2, LSCALE);
        o.w = pack4_e4m3(f3, LSCALE);
        g_L8[((size_t)rt * KB_TOTAL + kb) * 32 + lane] = o;
    }
}

// ---------------------------------------------------------------------------
// Step kernel for step s: blocks 0..127 finalize step s-1 (release counters);
// blocks 128.. run fp8 partial GEMM for step s (acquire-poll, then mainloop).
// ---------------------------------------------------------------------------
__device__ __forceinline__ void mma16832f8(float d[4], const uint4 a,
                                           unsigned b0, unsigned b1) {
    asm volatile(
        "mma.sync.aligned.m16n8k32.row.col.f32.e4m3.e4m3.f32 "
        "{%0,%1,%2,%3}, {%4,%5,%6,%7}, {%8,%9}, {%0,%1,%2,%3};\n"
        : "+f"(d[0]), "+f"(d[1]), "+f"(d[2]), "+f"(d[3])
        : "r"(a.x), "r"(a.y), "r"(a.z), "r"(a.w), "r"(b0), "r"(b1));
}

__global__ void __launch_bounds__(256, 6) step_fused(int s) {
    __shared__ uint4 sB[SLICES_PER_CTA * 32];   // 8 KB
    const int tid  = threadIdx.x;
    const int bid  = blockIdx.x;

    if (bid < FBLOCKS) {
        // ---- finalize partition: produce u_s / B8[s&1] from step s-1 ----
        if (s > 0) {
            finalize_rows(bid, tid, (s - 1) & 1, s & 1, nullptr, true);
            __threadfence();            // release: B8/U/P writes before counter bump
        }
        __syncthreads();
        if (tid == 0) atomicAdd(&g_finkg[bid >> 2], 1u);
        return;
    }

    const int pid = bid - FBLOCKS;                 // 0..4095
    const int kg  = pid >> 7;                      // 0..31
    const int rg  = pid & 127;                     // 0..127
    const int inb = s & 1;

    // ---- acquire: wait until the 4 finalize blocks covering kg are done ----
    {
        const unsigned target = 4u * (unsigned)(s + 1);   // monotonic within a replay
        if (tid == 0) {
            unsigned v;
            for (;;) {
                asm volatile("ld.acquire.gpu.global.u32 %0, [%1];"
                             : "=r"(v) : "l"(&g_finkg[kg]) : "memory");
                if (v >= target) break;
                __nanosleep(128);
            }
        }
        __syncthreads();
    }

    const int warp = tid >> 5;
    const int lane = tid & 31;
    const int rt  = rg * 8 + warp;
    const int kb0 = kg * SLICES_PER_CTA;

    {
        const uint4* __restrict__ Bg = reinterpret_cast<const uint4*>(g_B8[inb]) + kb0 * 32;
        #pragma unroll 2
        for (int i = tid; i < SLICES_PER_CTA * 32; i += 256) sB[i] = Bg[i];
    }
    __syncthreads();

    const uint4* __restrict__ Af = g_L8 + ((size_t)rt * KB_TOTAL + kb0) * 32 + lane;

    float d0[4] = {0.f, 0.f, 0.f, 0.f};   // cols 0..7
    float d1[4] = {0.f, 0.f, 0.f, 0.f};   // cols 8..15

    #pragma unroll
    for (int c = 0; c < SLICES_PER_CTA; c += 4) {
        const uint4 a0 = __ldcs(Af + (c + 0) * 32);
        const uint4 a1 = __ldcs(Af + (c + 1) * 32);
        const uint4 a2 = __ldcs(Af + (c + 2) * 32);
        const uint4 a3 = __ldcs(Af + (c + 3) * 32);
        const uint4 b0 = sB[(c + 0) * 32 + lane];
        const uint4 b1 = sB[(c + 1) * 32 + lane];
        const uint4 b2 = sB[(c + 2) * 32 + lane];
        const uint4 b3 = sB[(c + 3) * 32 + lane];
        mma16832f8(d0, a0, b0.x, b0.y);
        mma16832f8(d1, a0, b0.z, b0.w);
        mma16832f8(d0, a1, b1.x, b1.y);
        mma16832f8(d1, a1, b1.z, b1.w);
        mma16832f8(d0, a2, b2.x, b2.y);
        mma16832f8(d1, a2, b2.z, b2.w);
        mma16832f8(d0, a3, b3.x, b3.y);
        mma16832f8(d1, a3, b3.z, b3.w);
    }

    float* __restrict__ P = g_P[inb];
    const int g = lane >> 2, t2 = 2 * (lane & 3);
    const int r0 = rt * 16 + g, r1 = r0 + 8;
    #pragma unroll
    for (int h = 0; h < 2; h++) {
        const float* dd = h ? d1 : d0;
        const int cc = t2 + 8 * h;
        atomicAdd(&P[r0 * OUTF + cc],     dd[0]);
        atomicAdd(&P[r0 * OUTF + cc + 1], dd[1]);
        atomicAdd(&P[r1 * OUTF + cc],     dd[2]);
        atomicAdd(&P[r1 * OUTF + cc + 1], dd[3]);
    }
}

// ---------------------------------------------------------------------------
// Epilogue: finalize step 15 -> d_out; zero P[1]; reset counters.
// ---------------------------------------------------------------------------
__global__ void __launch_bounds__(256) epilogue(float* __restrict__ out) {
    finalize_rows(blockIdx.x, threadIdx.x, 1 /* 15&1 */, 0, out, false);
    if (blockIdx.x == 0 && threadIdx.x < 32) g_finkg[threadIdx.x] = 0u;
}

// ---------------------------------------------------------------------------
extern "C" void kernel_launch(void* const* d_in, const int* in_sizes, int n_in,
                              void* d_out, int out_size) {
    const float* F  = (const float*)d_in[0];
    const float* L  = (const float*)d_in[1];
    const float* W1 = (const float*)d_in[2];
    const float* b1 = (const float*)d_in[3];
    const float* W2 = (const float*)d_in[4];
    const float* b2 = (const float*)d_in[5];
    const float* Ws = (const float*)d_in[6];
    const float* bs = (const float*)d_in[7];

    prologue<<<INIT_CTAS + CONV_CTAS, 256>>>(L, F, W1, b1, W2, b2, Ws, bs);
    for (int s = 0; s < NSTEPS; s++)
        step_fused<<<FBLOCKS + RGROUPS * KSPLITS, 256>>>(s);
    epilogue<<<FBLOCKS, 256>>>((float*)d_out);
}

// round 15
// speedup vs baseline: 1.1062x; 1.1062x over previous
#include <cuda_runtime.h>
#include <cuda_bf16.h>
#include <cuda_fp16.h>

#define NTOK 16384
#define INF  512
#define HID  256
#define OUTF 16
#define NSTEPS 16
#define SIGMA2F 0.1f
#define LSCALE 16384.0f                 // 2^14: lifts L into e4m3 range
#define FIN_SCALE (SIGMA2F / LSCALE)
#define KSPLITS 32
#define KSEG (NTOK / KSPLITS)          // 512
#define KB_TOTAL (NTOK / 32)           // 512 32-k blocks
#define RT_TOTAL (NTOK / 16)           // 1024 row-tiles
#define SLICES_PER_CTA (KSEG / 32)     // 16
#define UNITS (128 * KSPLITS)          // 4096 (rg, kg) units
#define PERSIST_CTAS (148 * 6)         // 888
#define INIT_CTAS (NTOK / 8)           // 2048
#define CONV_CTAS (RT_TOTAL * 64)      // 65536

// Scratch (device globals: sanctioned, no allocation)
__device__ __align__(16) uint4          g_L8[(size_t)RT_TOTAL * KB_TOTAL * 32];  // 256 MB
__device__ __align__(16) float          g_U[2][NTOK * OUTF];                     // u fp32 master
__device__ __align__(16) unsigned char  g_B8[2][NTOK * OUTF];                    // u e4m3 B-frag-major
__device__ __align__(16) float          g_P[NTOK * OUTF];                        // partials (zero steady)
__device__ unsigned                     g_ticket[NSTEPS];                        // zero steady (reset by finalize)

// ---------------------------------------------------------------------------
__device__ __forceinline__ unsigned short e4m3x2_pack(float hi, float lo) {
    unsigned short r;
    asm("cvt.rn.satfinite.e4m3x2.f32 %0, %1, %2;" : "=h"(r) : "f"(hi), "f"(lo));
    return r;
}
__device__ __forceinline__ unsigned pack4_e4m3(float4 f, float s) {
    const unsigned lo = e4m3x2_pack(f.y * s, f.x * s);
    const unsigned hi = e4m3x2_pack(f.w * s, f.z * s);
    return lo | (hi << 16);
}

// write one fp32 value (row r = k index, col c) into e4m3 B-fragment layout
__device__ __forceinline__ void write_bfrag8(unsigned char* Bf, int r, int c, float v) {
    const int sl = r >> 5, p = r & 31;
    const int g = c & 7;
    const int ph = p & 15;
    const int lane = g * 4 + (ph >> 2);
    const int word = (p >> 4) + 2 * (c >> 3);
    const unsigned short q = e4m3x2_pack(0.0f, v);
    Bf[sl * 512 + lane * 16 + word * 4 + (ph & 3)] = (unsigned char)(q & 0xFF);
}

// ---------------------------------------------------------------------------
// Fused prologue: blocks [0, INIT_CTAS) = init_u0; rest = convert_L (overlap).
// ---------------------------------------------------------------------------
#define CV_PAD 264
struct ProSmem {
    union {
        struct { float fs[8][INF]; float hs[8][HID]; } init;   // 24 KB
        float cv[16][CV_PAD];                                  // ~16.9 KB
    };
};

__global__ void __launch_bounds__(256) prologue(
    const float* __restrict__ L,
    const float* __restrict__ F,  const float* __restrict__ W1, const float* __restrict__ b1,
    const float* __restrict__ W2, const float* __restrict__ b2,
    const float* __restrict__ Ws, const float* __restrict__ bs)
{
    __shared__ ProSmem sm;
    const int tid = threadIdx.x;

    if (blockIdx.x < INIT_CTAS) {
        // ================= init_u0 =================
        float (*fs)[INF] = sm.init.fs;
        float (*hs)[HID] = sm.init.hs;
        const int rbase = blockIdx.x * 8;

        {
            const float4* Fv = (const float4*)(F + (size_t)rbase * INF);
            float4* fsv = (float4*)&fs[0][0];
            #pragma unroll 4
            for (int i = tid; i < 8 * INF / 4; i += 256) fsv[i] = Fv[i];
        }
        __syncthreads();

        {
            const int j = tid;
            float acc[8];
            const float bb = b1[j];
            #pragma unroll
            for (int rr = 0; rr < 8; rr++) acc[rr] = bb;
            #pragma unroll 4
            for (int k = 0; k < INF; k++) {
                const float w = W1[k * HID + j];
                #pragma unroll
                for (int rr = 0; rr < 8; rr++) acc[rr] = fmaf(fs[rr][k], w, acc[rr]);
            }
            #pragma unroll
            for (int rr = 0; rr < 8; rr++) {
                const float x = acc[rr];
                hs[rr][j] = x > 0.0f ? x : expm1f(x);
            }
        }
        __syncthreads();

        if (tid < 8 * OUTF) {
            const int rr = tid >> 4, c = tid & 15;
            float s0 = bs[c] + b2[c], s1 = 0.f, s2 = 0.f, s3 = 0.f;
            #pragma unroll 4
            for (int k = 0; k < INF; k += 4) {
                s0 = fmaf(fs[rr][k + 0], Ws[(k + 0) * OUTF + c], s0);
                s1 = fmaf(fs[rr][k + 1], Ws[(k + 1) * OUTF + c], s1);
                s2 = fmaf(fs[rr][k + 2], Ws[(k + 2) * OUTF + c], s2);
                s3 = fmaf(fs[rr][k + 3], Ws[(k + 3) * OUTF + c], s3);
            }
            #pragma unroll 4
            for (int j = 0; j < HID; j += 4) {
                s0 = fmaf(hs[rr][j + 0], W2[(j + 0) * OUTF + c], s0);
                s1 = fmaf(hs[rr][j + 1], W2[(j + 1) * OUTF + c], s1);
                s2 = fmaf(hs[rr][j + 2], W2[(j + 2) * OUTF + c], s2);
                s3 = fmaf(hs[rr][j + 3], W2[(j + 3) * OUTF + c], s3);
            }
            const float s = (s0 + s1) + (s2 + s3);
            const int r = rbase + rr;
            g_U[0][r * OUTF + c] = s;
            write_bfrag8(g_B8[0], r, c, s);
        }
    } else {
        // ================= convert_L (k32 fragment layout) =================
        float (*s)[CV_PAD] = sm.cv;
        const int blk = blockIdx.x - INIT_CTAS;   // 0..65535
        const int rt = blk >> 6;
        const int kg = blk & 63;

        const float* __restrict__ src = L + (size_t)rt * 16 * NTOK + kg * 256;
        #pragma unroll 4
        for (int j = tid; j < 16 * 64; j += 256) {
            const int row = j >> 6, c4 = j & 63;
            const float4 v = __ldcs((const float4*)(src + (size_t)row * NTOK + c4 * 4));
            *(float4*)&s[row][c4 * 4] = v;
        }
        __syncthreads();

        const int warp = tid >> 5, lane = tid & 31;
        const int g = lane >> 2, t = lane & 3;
        const int kb = kg * 8 + warp;            // global 32-k block
        const int c = warp * 32 + 4 * t;         // local col base

        const float4 f0 = *(const float4*)&s[g][c];
        const float4 f1 = *(const float4*)&s[g + 8][c];
        const float4 f2 = *(const float4*)&s[g][c + 16];
        const float4 f3 = *(const float4*)&s[g + 8][c + 16];
        uint4 o;
        o.x = pack4_e4m3(f0, LSCALE);
        o.y = pack4_e4m3(f1, LSCALE);
        o.z = pack4_e4m3(f2, LSCALE);
        o.w = pack4_e4m3(f3, LSCALE);
        g_L8[((size_t)rt * KB_TOTAL + kb) * 32 + lane] = o;
    }
}

// ---------------------------------------------------------------------------
// Kernel 3: persistent ticketed fp8 partial GEMM. 888 CTAs pull (kg, rg)
// units (kg-major tickets -> sB reused across consecutive units; restage only
// on kg change). NO gpu-scope sync anywhere in this kernel.
// ---------------------------------------------------------------------------
__device__ __forceinline__ void mma16832f8(float d[4], const uint4 a,
                                           unsigned b0, unsigned b1) {
    asm volatile(
        "mma.sync.aligned.m16n8k32.row.col.f32.e4m3.e4m3.f32 "
        "{%0,%1,%2,%3}, {%4,%5,%6,%7}, {%8,%9}, {%0,%1,%2,%3};\n"
        : "+f"(d[0]), "+f"(d[1]), "+f"(d[2]), "+f"(d[3])
        : "r"(a.x), "r"(a.y), "r"(a.z), "r"(a.w), "r"(b0), "r"(b1));
}

__global__ void __launch_bounds__(256, 6) step_partial(int inb, int step) {
    __shared__ uint4 sB[SLICES_PER_CTA * 32];   // 8 KB
    __shared__ unsigned s_t;

    const int tid  = threadIdx.x;
    const int warp = tid >> 5;
    const int lane = tid & 31;
    const int g = lane >> 2, t2 = 2 * (lane & 3);

    int cur_kg = -1;

    for (;;) {
        if (tid == 0) s_t = atomicAdd(&g_ticket[step], 1u);
        __syncthreads();                       // publish s_t; prior sB reads are done
        const unsigned u = s_t;
        if (u >= UNITS) return;

        const int kg = u >> 7;                 // kg-major: 128 consecutive tickets share kg
        const int rg = u & 127;
        const int kb0 = kg * SLICES_PER_CTA;
        const int rt  = rg * 8 + warp;

        if (kg != cur_kg) {
            const uint4* __restrict__ Bg =
                reinterpret_cast<const uint4*>(g_B8[inb]) + kb0 * 32;
            #pragma unroll 2
            for (int i = tid; i < SLICES_PER_CTA * 32; i += 256) sB[i] = Bg[i];
            cur_kg = kg;
            __syncthreads();
        }

        const uint4* __restrict__ Af = g_L8 + ((size_t)rt * KB_TOTAL + kb0) * 32 + lane;

        float d0[4] = {0.f, 0.f, 0.f, 0.f};   // cols 0..7
        float d1[4] = {0.f, 0.f, 0.f, 0.f};   // cols 8..15

        #pragma unroll
        for (int c = 0; c < SLICES_PER_CTA; c += 4) {
            const uint4 a0 = __ldcs(Af + (c + 0) * 32);
            const uint4 a1 = __ldcs(Af + (c + 1) * 32);
            const uint4 a2 = __ldcs(Af + (c + 2) * 32);
            const uint4 a3 = __ldcs(Af + (c + 3) * 32);
            const uint4 b0 = sB[(c + 0) * 32 + lane];
            const uint4 b1 = sB[(c + 1) * 32 + lane];
            const uint4 b2 = sB[(c + 2) * 32 + lane];
            const uint4 b3 = sB[(c + 3) * 32 + lane];
            mma16832f8(d0, a0, b0.x, b0.y);
            mma16832f8(d1, a0, b0.z, b0.w);
            mma16832f8(d0, a1, b1.x, b1.y);
            mma16832f8(d1, a1, b1.z, b1.w);
            mma16832f8(d0, a2, b2.x, b2.y);
            mma16832f8(d1, a2, b2.z, b2.w);
            mma16832f8(d0, a3, b3.x, b3.y);
            mma16832f8(d1, a3, b3.z, b3.w);
        }

        const int r0 = rt * 16 + g, r1 = r0 + 8;
        #pragma unroll
        for (int h = 0; h < 2; h++) {
            const float* dd = h ? d1 : d0;
            const int cc = t2 + 8 * h;
            atomicAdd(&g_P[r0 * OUTF + cc],     dd[0]);
            atomicAdd(&g_P[r0 * OUTF + cc + 1], dd[1]);
            atomicAdd(&g_P[r1 * OUTF + cc],     dd[2]);
            atomicAdd(&g_P[r1 * OUTF + cc + 1], dd[3]);
        }
    }
}

// ---------------------------------------------------------------------------
// Kernel 4: finalize. u_out = u_in - (sigma2/LSCALE) * P; rezero P; emit B8;
// reset this step's ticket counter (replay idempotence).
// ---------------------------------------------------------------------------
__global__ void __launch_bounds__(256) step_finalize(int inb, int outb, int step,
                                                     float* final_dst) {
    const int idx = blockIdx.x * 256 + threadIdx.x;   // 0..32767
    const int r = idx >> 1;
    const int c0 = (idx & 1) * 8;
    if (idx == 0) g_ticket[step] = 0u;

    const float* __restrict__ Ui = g_U[inb] + r * OUTF + c0;
    float* __restrict__ Uo = g_U[outb] + r * OUTF + c0;
    float* __restrict__ P  = g_P + r * OUTF + c0;

    float v[8];
    #pragma unroll
    for (int i = 0; i < 2; i++) {
        float4 u4 = *(const float4*)(Ui + 4 * i);
        float4 p4 = *(const float4*)(P + 4 * i);
        v[4*i+0] = u4.x - FIN_SCALE * p4.x;
        v[4*i+1] = u4.y - FIN_SCALE * p4.y;
        v[4*i+2] = u4.z - FIN_SCALE * p4.z;
        v[4*i+3] = u4.w - FIN_SCALE * p4.w;
        *(float4*)(Uo + 4 * i) = make_float4(v[4*i+0], v[4*i+1], v[4*i+2], v[4*i+3]);
        *(float4*)(P + 4 * i) = make_float4(0.f, 0.f, 0.f, 0.f);
        if (final_dst) *(float4*)(final_dst + r * OUTF + c0 + 4 * i)
            = make_float4(v[4*i+0], v[4*i+1], v[4*i+2], v[4*i+3]);
    }
    unsigned char* __restrict__ Bf = g_B8[outb];
    #pragma unroll
    for (int c = 0; c < 8; c++) write_bfrag8(Bf, r, c0 + c, v[c]);
}

// ---------------------------------------------------------------------------
extern "C" void kernel_launch(void* const* d_in, const int* in_sizes, int n_in,
                              void* d_out, int out_size) {
    const float* F  = (const float*)d_in[0];
    const float* L  = (const float*)d_in[1];
    const float* W1 = (const float*)d_in[2];
    const float* b1 = (const float*)d_in[3];
    const float* W2 = (const float*)d_in[4];
    const float* b2 = (const float*)d_in[5];
    const float* Ws = (const float*)d_in[6];
    const float* bs = (const float*)d_in[7];

    prologue<<<INIT_CTAS + CONV_CTAS, 256>>>(L, F, W1, b1, W2, b2, Ws, bs);
    for (int s = 0; s < NSTEPS; s++) {
        step_partial<<<PERSIST_CTAS, 256>>>(s & 1, s);
        step_finalize<<<NTOK * 2 / 256, 256>>>(s & 1, (s + 1) & 1, s,
                                               s == NSTEPS - 1 ? (float*)d_out : nullptr);
    }
}

// round 16
// speedup vs baseline: 1.1483x; 1.0380x over previous
#include <cuda_runtime.h>
#include <cuda_bf16.h>
#include <cuda_fp16.h>

#define NTOK 16384
#define INF  512
#define HID  256
#define OUTF 16
#define NSTEPS 16
#define SIGMA2F 0.1f
#define LSCALE 16384.0f                 // 2^14: lifts L into e4m3 range
#define FIN_SCALE (SIGMA2F / LSCALE)
#define KSPLITS 32
#define KSEG (NTOK / KSPLITS)          // 512
#define KB_TOTAL (NTOK / 32)           // 512 32-k blocks
#define RT_TOTAL (NTOK / 16)           // 1024 row-tiles
#define SLICES_PER_CTA (KSEG / 32)     // 16
#define INIT_CTAS (NTOK / 8)           // 2048
#define CONV_CTAS (RT_TOTAL * 64)      // 65536

// Scratch (device globals: sanctioned, no allocation)
// g_L8: L e4m3, k32-fragment-major: block (rt, kb) -> 512B, lane l -> uint4
__device__ __align__(16) uint4          g_L8[(size_t)RT_TOTAL * KB_TOTAL * 32];  // 256 MB
__device__ __align__(16) float          g_U[2][NTOK * OUTF];                     // u fp32 master
__device__ __align__(16) unsigned char  g_B8[2][NTOK * OUTF];                    // u e4m3 B-frag-major
__device__ __align__(16) float          g_P[NTOK * OUTF];                        // partials (zero steady)

// ---------------------------------------------------------------------------
__device__ __forceinline__ unsigned short e4m3x2_pack(float hi, float lo) {
    unsigned short r;
    asm("cvt.rn.satfinite.e4m3x2.f32 %0, %1, %2;" : "=h"(r) : "f"(hi), "f"(lo));
    return r;
}
__device__ __forceinline__ unsigned pack4_e4m3(float4 f, float s) {
    const unsigned lo = e4m3x2_pack(f.y * s, f.x * s);
    const unsigned hi = e4m3x2_pack(f.w * s, f.z * s);
    return lo | (hi << 16);
}

// write one fp32 value (row r = k index, col c) into e4m3 B-fragment layout
__device__ __forceinline__ void write_bfrag8(unsigned char* Bf, int r, int c, float v) {
    const int sl = r >> 5, p = r & 31;
    const int g = c & 7;
    const int ph = p & 15;
    const int lane = g * 4 + (ph >> 2);
    const int word = (p >> 4) + 2 * (c >> 3);
    const unsigned short q = e4m3x2_pack(0.0f, v);
    Bf[sl * 512 + lane * 16 + word * 4 + (ph & 3)] = (unsigned char)(q & 0xFF);
}

// ---------------------------------------------------------------------------
// Fused prologue: blocks [0, INIT_CTAS) = init_u0; rest = convert_L (overlap).
// ---------------------------------------------------------------------------
#define CV_PAD 264
struct ProSmem {
    union {
        struct { float fs[8][INF]; float hs[8][HID]; } init;   // 24 KB
        float cv[16][CV_PAD];                                  // ~16.9 KB
    };
};

__global__ void __launch_bounds__(256) prologue(
    const float* __restrict__ L,
    const float* __restrict__ F,  const float* __restrict__ W1, const float* __restrict__ b1,
    const float* __restrict__ W2, const float* __restrict__ b2,
    const float* __restrict__ Ws, const float* __restrict__ bs)
{
    __shared__ ProSmem sm;
    const int tid = threadIdx.x;

    if (blockIdx.x < INIT_CTAS) {
        // ================= init_u0 =================
        float (*fs)[INF] = sm.init.fs;
        float (*hs)[HID] = sm.init.hs;
        const int rbase = blockIdx.x * 8;

        {
            const float4* Fv = (const float4*)(F + (size_t)rbase * INF);
            float4* fsv = (float4*)&fs[0][0];
            #pragma unroll 4
            for (int i = tid; i < 8 * INF / 4; i += 256) fsv[i] = Fv[i];
        }
        __syncthreads();

        {
            const int j = tid;
            float acc[8];
            const float bb = b1[j];
            #pragma unroll
            for (int rr = 0; rr < 8; rr++) acc[rr] = bb;
            #pragma unroll 4
            for (int k = 0; k < INF; k++) {
                const float w = W1[k * HID + j];
                #pragma unroll
                for (int rr = 0; rr < 8; rr++) acc[rr] = fmaf(fs[rr][k], w, acc[rr]);
            }
            #pragma unroll
            for (int rr = 0; rr < 8; rr++) {
                const float x = acc[rr];
                hs[rr][j] = x > 0.0f ? x : expm1f(x);
            }
        }
        __syncthreads();

        if (tid < 8 * OUTF) {
            const int rr = tid >> 4, c = tid & 15;
            float s0 = bs[c] + b2[c], s1 = 0.f, s2 = 0.f, s3 = 0.f;
            #pragma unroll 4
            for (int k = 0; k < INF; k += 4) {
                s0 = fmaf(fs[rr][k + 0], Ws[(k + 0) * OUTF + c], s0);
                s1 = fmaf(fs[rr][k + 1], Ws[(k + 1) * OUTF + c], s1);
                s2 = fmaf(fs[rr][k + 2], Ws[(k + 2) * OUTF + c], s2);
                s3 = fmaf(fs[rr][k + 3], Ws[(k + 3) * OUTF + c], s3);
            }
            #pragma unroll 4
            for (int j = 0; j < HID; j += 4) {
                s0 = fmaf(hs[rr][j + 0], W2[(j + 0) * OUTF + c], s0);
                s1 = fmaf(hs[rr][j + 1], W2[(j + 1) * OUTF + c], s1);
                s2 = fmaf(hs[rr][j + 2], W2[(j + 2) * OUTF + c], s2);
                s3 = fmaf(hs[rr][j + 3], W2[(j + 3) * OUTF + c], s3);
            }
            const float s = (s0 + s1) + (s2 + s3);
            const int r = rbase + rr;
            g_U[0][r * OUTF + c] = s;
            write_bfrag8(g_B8[0], r, c, s);
        }
    } else {
        // ================= convert_L (k32 fragment layout) =================
        float (*s)[CV_PAD] = sm.cv;
        const int blk = blockIdx.x - INIT_CTAS;   // 0..65535
        const int rt = blk >> 6;
        const int kg = blk & 63;

        const float* __restrict__ src = L + (size_t)rt * 16 * NTOK + kg * 256;
        #pragma unroll 4
        for (int j = tid; j < 16 * 64; j += 256) {
            const int row = j >> 6, c4 = j & 63;
            const float4 v = __ldcs((const float4*)(src + (size_t)row * NTOK + c4 * 4));
            *(float4*)&s[row][c4 * 4] = v;
        }
        __syncthreads();

        const int warp = tid >> 5, lane = tid & 31;
        const int g = lane >> 2, t = lane & 3;
        const int kb = kg * 8 + warp;            // global 32-k block
        const int c = warp * 32 + 4 * t;         // local col base

        const float4 f0 = *(const float4*)&s[g][c];
        const float4 f1 = *(const float4*)&s[g + 8][c];
        const float4 f2 = *(const float4*)&s[g][c + 16];
        const float4 f3 = *(const float4*)&s[g + 8][c + 16];
        uint4 o;
        o.x = pack4_e4m3(f0, LSCALE);
        o.y = pack4_e4m3(f1, LSCALE);
        o.z = pack4_e4m3(f2, LSCALE);
        o.w = pack4_e4m3(f3, LSCALE);
        g_L8[((size_t)rt * KB_TOTAL + kb) * 32 + lane] = o;
    }
}

// ---------------------------------------------------------------------------
// Kernel 3: partial GEMM, full fp8 (e4m3 x e4m3, m16n8k32). Static grid
// (128, 32), 8 warps/CTA — the best-measured shape (R11). Sync-free.
// ---------------------------------------------------------------------------
__device__ __forceinline__ void mma16832f8(float d[4], const uint4 a,
                                           unsigned b0, unsigned b1) {
    asm volatile(
        "mma.sync.aligned.m16n8k32.row.col.f32.e4m3.e4m3.f32 "
        "{%0,%1,%2,%3}, {%4,%5,%6,%7}, {%8,%9}, {%0,%1,%2,%3};\n"
        : "+f"(d[0]), "+f"(d[1]), "+f"(d[2]), "+f"(d[3])
        : "r"(a.x), "r"(a.y), "r"(a.z), "r"(a.w), "r"(b0), "r"(b1));
}

__global__ void __launch_bounds__(256, 6) step_partial(int inb) {
    __shared__ uint4 sB[SLICES_PER_CTA * 32];   // 8 KB: e4m3 B frags for this K-range

    const int tid  = threadIdx.x;
    const int warp = tid >> 5;
    const int lane = tid & 31;

    const int rt  = blockIdx.x * 8 + warp;              // row-tile 0..1023
    const int kb0 = blockIdx.y * SLICES_PER_CTA;        // first 32-k block

    {
        const uint4* __restrict__ Bg = reinterpret_cast<const uint4*>(g_B8[inb]) + kb0 * 32;
        #pragma unroll 2
        for (int i = tid; i < SLICES_PER_CTA * 32; i += 256) sB[i] = Bg[i];
    }
    __syncthreads();

    const uint4* __restrict__ Af = g_L8 + ((size_t)rt * KB_TOTAL + kb0) * 32 + lane;

    float d0[4] = {0.f, 0.f, 0.f, 0.f};   // cols 0..7
    float d1[4] = {0.f, 0.f, 0.f, 0.f};   // cols 8..15

    #pragma unroll 2
    for (int c = 0; c < SLICES_PER_CTA; c += 2) {
        const uint4 a0 = __ldcs(Af + (c + 0) * 32);
        const uint4 a1 = __ldcs(Af + (c + 1) * 32);
        const uint4 b0 = sB[(c + 0) * 32 + lane];
        const uint4 b1 = sB[(c + 1) * 32 + lane];
        mma16832f8(d0, a0, b0.x, b0.y);
        mma16832f8(d1, a0, b0.z, b0.w);
        mma16832f8(d0, a1, b1.x, b1.y);
        mma16832f8(d1, a1, b1.z, b1.w);
    }

    const int g = lane >> 2, t2 = 2 * (lane & 3);
    const int r0 = rt * 16 + g, r1 = r0 + 8;
    #pragma unroll
    for (int h = 0; h < 2; h++) {
        const float* dd = h ? d1 : d0;
        const int cc = t2 + 8 * h;
        atomicAdd(&g_P[r0 * OUTF + cc],     dd[0]);
        atomicAdd(&g_P[r0 * OUTF + cc + 1], dd[1]);
        atomicAdd(&g_P[r1 * OUTF + cc],     dd[2]);
        atomicAdd(&g_P[r1 * OUTF + cc + 1], dd[3]);
    }
}

// ---------------------------------------------------------------------------
// Kernel 4: finalize. u_out = u_in - (sigma2/LSCALE) * P; rezero P; emit B8.
// 4 threads per row (65536 threads, 256 blocks): one float4 per array per
// thread — halves the latency chain, doubles blocks/SM vs 2-thread version.
// ---------------------------------------------------------------------------
__global__ void __launch_bounds__(256) step_finalize(int inb, int outb, float* final_dst) {
    const int idx = blockIdx.x * 256 + threadIdx.x;   // 0..65535
    const int r = idx >> 2;
    const int c0 = (idx & 3) * 4;

    const float* __restrict__ Ui = g_U[inb] + r * OUTF + c0;
    float* __restrict__ Uo = g_U[outb] + r * OUTF + c0;
    float* __restrict__ P  = g_P + r * OUTF + c0;

    const float4 u4 = *(const float4*)Ui;
    const float4 p4 = *(const float4*)P;
    float v[4];
    v[0] = u4.x - FIN_SCALE * p4.x;
    v[1] = u4.y - FIN_SCALE * p4.y;
    v[2] = u4.z - FIN_SCALE * p4.z;
    v[3] = u4.w - FIN_SCALE * p4.w;
    *(float4*)Uo = make_float4(v[0], v[1], v[2], v[3]);
    *(float4*)P  = make_float4(0.f, 0.f, 0.f, 0.f);
    if (final_dst)
        *(float4*)(final_dst + r * OUTF + c0) = make_float4(v[0], v[1], v[2], v[3]);

    unsigned char* __restrict__ Bf = g_B8[outb];
    #pragma unroll
    for (int c = 0; c < 4; c++) write_bfrag8(Bf, r, c0 + c, v[c]);
}

// ---------------------------------------------------------------------------
extern "C" void kernel_launch(void* const* d_in, const int* in_sizes, int n_in,
                              void* d_out, int out_size) {
    const float* F  = (const float*)d_in[0];
    const float* L  = (const float*)d_in[1];
    const float* W1 = (const float*)d_in[2];
    const float* b1 = (const float*)d_in[3];
    const float* W2 = (const float*)d_in[4];
    const float* b2 = (const float*)d_in[5];
    const float* Ws = (const float*)d_in[6];
    const float* bs = (const float*)d_in[7];

    prologue<<<INIT_CTAS + CONV_CTAS, 256>>>(L, F, W1, b1, W2, b2, Ws, bs);
    for (int s = 0; s < NSTEPS; s++) {
        dim3 grid(RT_TOTAL / 8, KSPLITS);
        step_partial<<<grid, 256>>>(s & 1);
        step_finalize<<<NTOK * 4 / 256, 256>>>(s & 1, (s + 1) & 1,
                                               s == NSTEPS - 1 ? (float*)d_out : nullptr);
    }
}

// round 17
// speedup vs baseline: 1.1873x; 1.0340x over previous
#include <cuda_runtime.h>
#include <cuda_bf16.h>
#include <cuda_fp16.h>

#define NTOK 16384
#define INF  512
#define HID  256
#define OUTF 16
#define NSTEPS 16
#define SIGMA2F 0.1f
#define LSCALE 16384.0f                 // 2^14: lifts L into e4m3 range
#define FIN_SCALE (SIGMA2F / LSCALE)
#define KSPLITS 32
#define KSEG (NTOK / KSPLITS)          // 512
#define KB_TOTAL (NTOK / 32)           // 512 32-k blocks
#define RT_TOTAL (NTOK / 16)           // 1024 row-tiles
#define SLICES_PER_CTA (KSEG / 32)     // 16
#define INIT_CTAS (NTOK / 8)           // 2048
#define CONV_CTAS (RT_TOTAL * 64)      // 65536

// Scratch (device globals: sanctioned, no allocation)
// g_L8: L e4m3, k32-fragment-major: block (rt, kb) -> 512B, lane l -> uint4
__device__ __align__(16) uint4          g_L8[(size_t)RT_TOTAL * KB_TOTAL * 32];  // 256 MB
__device__ __align__(16) float          g_U[2][NTOK * OUTF];                     // u fp32 master
__device__ __align__(16) unsigned char  g_B8[2][NTOK * OUTF];                    // u e4m3 B-frag-major
__device__ __align__(16) float          g_P[NTOK * OUTF];                        // partials (zero steady)

// ---------------------------------------------------------------------------
__device__ __forceinline__ unsigned short e4m3x2_pack(float hi, float lo) {
    unsigned short r;
    asm("cvt.rn.satfinite.e4m3x2.f32 %0, %1, %2;" : "=h"(r) : "f"(hi), "f"(lo));
    return r;
}
__device__ __forceinline__ unsigned pack4_e4m3(float4 f, float s) {
    const unsigned lo = e4m3x2_pack(f.y * s, f.x * s);
    const unsigned hi = e4m3x2_pack(f.w * s, f.z * s);
    return lo | (hi << 16);
}

// write one fp32 value (row r = k index, col c) into e4m3 B-fragment layout
__device__ __forceinline__ void write_bfrag8(unsigned char* Bf, int r, int c, float v) {
    const int sl = r >> 5, p = r & 31;
    const int g = c & 7;
    const int ph = p & 15;
    const int lane = g * 4 + (ph >> 2);
    const int word = (p >> 4) + 2 * (c >> 3);
    const unsigned short q = e4m3x2_pack(0.0f, v);
    Bf[sl * 512 + lane * 16 + word * 4 + (ph & 3)] = (unsigned char)(q & 0xFF);
}

// ---------------------------------------------------------------------------
// Fused prologue: blocks [0, INIT_CTAS) = init_u0; rest = convert_L (overlap).
// ---------------------------------------------------------------------------
#define CV_PAD 264
struct ProSmem {
    union {
        struct { float fs[8][INF]; float hs[8][HID]; } init;   // 24 KB
        float cv[16][CV_PAD];                                  // ~16.9 KB
    };
};

__global__ void __launch_bounds__(256) prologue(
    const float* __restrict__ L,
    const float* __restrict__ F,  const float* __restrict__ W1, const float* __restrict__ b1,
    const float* __restrict__ W2, const float* __restrict__ b2,
    const float* __restrict__ Ws, const float* __restrict__ bs)
{
    __shared__ ProSmem sm;
    const int tid = threadIdx.x;

    if (blockIdx.x < INIT_CTAS) {
        // ================= init_u0 =================
        float (*fs)[INF] = sm.init.fs;
        float (*hs)[HID] = sm.init.hs;
        const int rbase = blockIdx.x * 8;

        {
            const float4* Fv = (const float4*)(F + (size_t)rbase * INF);
            float4* fsv = (float4*)&fs[0][0];
            #pragma unroll 4
            for (int i = tid; i < 8 * INF / 4; i += 256) fsv[i] = Fv[i];
        }
        __syncthreads();

        {
            const int j = tid;
            float acc[8];
            const float bb = b1[j];
            #pragma unroll
            for (int rr = 0; rr < 8; rr++) acc[rr] = bb;
            #pragma unroll 4
            for (int k = 0; k < INF; k++) {
                const float w = W1[k * HID + j];
                #pragma unroll
                for (int rr = 0; rr < 8; rr++) acc[rr] = fmaf(fs[rr][k], w, acc[rr]);
            }
            #pragma unroll
            for (int rr = 0; rr < 8; rr++) {
                const float x = acc[rr];
                hs[rr][j] = x > 0.0f ? x : expm1f(x);
            }
        }
        __syncthreads();

        if (tid < 8 * OUTF) {
            const int rr = tid >> 4, c = tid & 15;
            float s0 = bs[c] + b2[c], s1 = 0.f, s2 = 0.f, s3 = 0.f;
            #pragma unroll 4
            for (int k = 0; k < INF; k += 4) {
                s0 = fmaf(fs[rr][k + 0], Ws[(k + 0) * OUTF + c], s0);
                s1 = fmaf(fs[rr][k + 1], Ws[(k + 1) * OUTF + c], s1);
                s2 = fmaf(fs[rr][k + 2], Ws[(k + 2) * OUTF + c], s2);
                s3 = fmaf(fs[rr][k + 3], Ws[(k + 3) * OUTF + c], s3);
            }
            #pragma unroll 4
            for (int j = 0; j < HID; j += 4) {
                s0 = fmaf(hs[rr][j + 0], W2[(j + 0) * OUTF + c], s0);
                s1 = fmaf(hs[rr][j + 1], W2[(j + 1) * OUTF + c], s1);
                s2 = fmaf(hs[rr][j + 2], W2[(j + 2) * OUTF + c], s2);
                s3 = fmaf(hs[rr][j + 3], W2[(j + 3) * OUTF + c], s3);
            }
            const float s = (s0 + s1) + (s2 + s3);
            const int r = rbase + rr;
            g_U[0][r * OUTF + c] = s;
            write_bfrag8(g_B8[0], r, c, s);
        }
    } else {
        // ================= convert_L (k32 fragment layout) =================
        float (*s)[CV_PAD] = sm.cv;
        const int blk = blockIdx.x - INIT_CTAS;   // 0..65535
        const int rt = blk >> 6;
        const int kg = blk & 63;

        const float* __restrict__ src = L + (size_t)rt * 16 * NTOK + kg * 256;
        #pragma unroll 4
        for (int j = tid; j < 16 * 64; j += 256) {
            const int row = j >> 6, c4 = j & 63;
            const float4 v = __ldcs((const float4*)(src + (size_t)row * NTOK + c4 * 4));
            *(float4*)&s[row][c4 * 4] = v;
        }
        __syncthreads();

        const int warp = tid >> 5, lane = tid & 31;
        const int g = lane >> 2, t = lane & 3;
        const int kb = kg * 8 + warp;            // global 32-k block
        const int c = warp * 32 + 4 * t;         // local col base

        const float4 f0 = *(const float4*)&s[g][c];
        const float4 f1 = *(const float4*)&s[g + 8][c];
        const float4 f2 = *(const float4*)&s[g][c + 16];
        const float4 f3 = *(const float4*)&s[g + 8][c + 16];
        uint4 o;
        o.x = pack4_e4m3(f0, LSCALE);
        o.y = pack4_e4m3(f1, LSCALE);
        o.z = pack4_e4m3(f2, LSCALE);
        o.w = pack4_e4m3(f3, LSCALE);
        g_L8[((size_t)rt * KB_TOTAL + kb) * 32 + lane] = o;
    }
}

// ---------------------------------------------------------------------------
// Kernel 3: partial GEMM, full fp8 (e4m3 x e4m3, m16n8k32). Static grid
// (128, 32), 8 warps/CTA. ZIG-ZAG kg traversal across steps: odd steps visit
// kg in reverse so step s+1 re-reads the lines step s left in L2 (126 MB,
// not flushed across launches). A-loads use default policy (LRU retention).
// ---------------------------------------------------------------------------
__device__ __forceinline__ void mma16832f8(float d[4], const uint4 a,
                                           unsigned b0, unsigned b1) {
    asm volatile(
        "mma.sync.aligned.m16n8k32.row.col.f32.e4m3.e4m3.f32 "
        "{%0,%1,%2,%3}, {%4,%5,%6,%7}, {%8,%9}, {%0,%1,%2,%3};\n"
        : "+f"(d[0]), "+f"(d[1]), "+f"(d[2]), "+f"(d[3])
        : "r"(a.x), "r"(a.y), "r"(a.z), "r"(a.w), "r"(b0), "r"(b1));
}

__global__ void __launch_bounds__(256, 6) step_partial(int inb, int rev) {
    __shared__ uint4 sB[SLICES_PER_CTA * 32];   // 8 KB: e4m3 B frags for this K-range

    const int tid  = threadIdx.x;
    const int warp = tid >> 5;
    const int lane = tid & 31;

    const int kgi = rev ? (KSPLITS - 1 - (int)blockIdx.y) : (int)blockIdx.y;
    const int rt  = blockIdx.x * 8 + warp;              // row-tile 0..1023
    const int kb0 = kgi * SLICES_PER_CTA;               // first 32-k block

    {
        const uint4* __restrict__ Bg = reinterpret_cast<const uint4*>(g_B8[inb]) + kb0 * 32;
        #pragma unroll 2
        for (int i = tid; i < SLICES_PER_CTA * 32; i += 256) sB[i] = Bg[i];
    }
    __syncthreads();

    const uint4* __restrict__ Af = g_L8 + ((size_t)rt * KB_TOTAL + kb0) * 32 + lane;

    float d0[4] = {0.f, 0.f, 0.f, 0.f};   // cols 0..7
    float d1[4] = {0.f, 0.f, 0.f, 0.f};   // cols 8..15

    #pragma unroll 2
    for (int c = 0; c < SLICES_PER_CTA; c += 2) {
        const uint4 a0 = Af[(c + 0) * 32];        // default policy: keep in L2
        const uint4 a1 = Af[(c + 1) * 32];
        const uint4 b0 = sB[(c + 0) * 32 + lane];
        const uint4 b1 = sB[(c + 1) * 32 + lane];
        mma16832f8(d0, a0, b0.x, b0.y);
        mma16832f8(d1, a0, b0.z, b0.w);
        mma16832f8(d0, a1, b1.x, b1.y);
        mma16832f8(d1, a1, b1.z, b1.w);
    }

    const int g = lane >> 2, t2 = 2 * (lane & 3);
    const int r0 = rt * 16 + g, r1 = r0 + 8;
    #pragma unroll
    for (int h = 0; h < 2; h++) {
        const float* dd = h ? d1 : d0;
        const int cc = t2 + 8 * h;
        atomicAdd(&g_P[r0 * OUTF + cc],     dd[0]);
        atomicAdd(&g_P[r0 * OUTF + cc + 1], dd[1]);
        atomicAdd(&g_P[r1 * OUTF + cc],     dd[2]);
        atomicAdd(&g_P[r1 * OUTF + cc + 1], dd[3]);
    }
}

// ---------------------------------------------------------------------------
// Kernel 4: finalize. u_out = u_in - (sigma2/LSCALE) * P; rezero P; emit B8.
// 4 threads per row (65536 threads, 256 blocks).
// ---------------------------------------------------------------------------
__global__ void __launch_bounds__(256) step_finalize(int inb, int outb, float* final_dst) {
    const int idx = blockIdx.x * 256 + threadIdx.x;   // 0..65535
    const int r = idx >> 2;
    const int c0 = (idx & 3) * 4;

    const float* __restrict__ Ui = g_U[inb] + r * OUTF + c0;
    float* __restrict__ Uo = g_U[outb] + r * OUTF + c0;
    float* __restrict__ P  = g_P + r * OUTF + c0;

    const float4 u4 = *(const float4*)Ui;
    const float4 p4 = *(const float4*)P;
    float v[4];
    v[0] = u4.x - FIN_SCALE * p4.x;
    v[1] = u4.y - FIN_SCALE * p4.y;
    v[2] = u4.z - FIN_SCALE * p4.z;
    v[3] = u4.w - FIN_SCALE * p4.w;
    *(float4*)Uo = make_float4(v[0], v[1], v[2], v[3]);
    *(float4*)P  = make_float4(0.f, 0.f, 0.f, 0.f);
    if (final_dst)
        *(float4*)(final_dst + r * OUTF + c0) = make_float4(v[0], v[1], v[2], v[3]);

    unsigned char* __restrict__ Bf = g_B8[outb];
    #pragma unroll
    for (int c = 0; c < 4; c++) write_bfrag8(Bf, r, c0 + c, v[c]);
}

// ---------------------------------------------------------------------------
extern "C" void kernel_launch(void* const* d_in, const int* in_sizes, int n_in,
                              void* d_out, int out_size) {
    const float* F  = (const float*)d_in[0];
    const float* L  = (const float*)d_in[1];
    const float* W1 = (const float*)d_in[2];
    const float* b1 = (const float*)d_in[3];
    const float* W2 = (const float*)d_in[4];
    const float* b2 = (const float*)d_in[5];
    const float* Ws = (const float*)d_in[6];
    const float* bs = (const float*)d_in[7];

    prologue<<<INIT_CTAS + CONV_CTAS, 256>>>(L, F, W1, b1, W2, b2, Ws, bs);
    for (int s = 0; s < NSTEPS; s++) {
        dim3 grid(RT_TOTAL / 8, KSPLITS);
        // zig-zag: odd steps reverse kg order to harvest L2 retention
        step_partial<<<grid, 256>>>(s & 1, s & 1);
        step_finalize<<<NTOK * 4 / 256, 256>>>(s & 1, (s + 1) & 1,
                                               s == NSTEPS - 1 ? (float*)d_out : nullptr);
    }
}